// round 11
// baseline (speedup 1.0000x reference)
#include <cuda_runtime.h>
#include <cstdint>

// ---------------- problem constants ----------------
#define N_NODES 100000
#define N_EDGES 1600000
#define EMB     64
#define HID     128
#define NEG     0.2f

// ---------------- device scratch (no allocs allowed) ----------------
__device__ float g_xl[N_NODES * EMB];
__device__ float g_xr[N_NODES * EMB];
__device__ float g_h [N_NODES * EMB];
__device__ float g_h2[N_NODES * EMB];
__device__ int   g_deg[N_NODES];
__device__ int   g_off[N_NODES];
__device__ int   g_cur[N_NODES];
__device__ unsigned long long g_es[N_EDGES];  // packed (ea<<32 | src), sorted by dst
__device__ float g_easum;

// ---------------- helpers ----------------
__device__ __forceinline__ float leaky(float a) {
    return fmaxf(a, NEG * a);           // valid for 0 < NEG < 1
}

// ---------------- CSR build ----------------
__global__ void k_hist(const int* __restrict__ ei) {
    for (int e = blockIdx.x * blockDim.x + threadIdx.x; e < N_EDGES;
         e += gridDim.x * blockDim.x)
        atomicAdd(&g_deg[ei[N_EDGES + e]], 1);
}

// Single-block exclusive scan of degrees -> offsets (+ cursor copy).
__global__ __launch_bounds__(1024) void k_scan() {
    __shared__ int part[1024];
    int t = threadIdx.x;
    const int chunk = (N_NODES + 1023) / 1024;     // 98
    int lo = t * chunk;
    int hi = min(lo + chunk, N_NODES);
    int s = 0;
    for (int i = lo; i < hi; i++) s += g_deg[i];
    part[t] = s;
    __syncthreads();
    for (int o = 1; o < 1024; o <<= 1) {
        int v = (t >= o) ? part[t - o] : 0;
        __syncthreads();
        part[t] += v;
        __syncthreads();
    }
    int base = (t == 0) ? 0 : part[t - 1];
    for (int i = lo; i < hi; i++) {
        g_off[i] = base;
        g_cur[i] = base;
        base += g_deg[i];
    }
}

// Scatter edges into dst-sorted order; also accumulates sum(edge_attr).
__global__ void k_scatter(const int* __restrict__ ei, const float* __restrict__ ea) {
    float s = 0.0f;
    for (int e = blockIdx.x * blockDim.x + threadIdx.x; e < N_EDGES;
         e += gridDim.x * blockDim.x) {
        int src = ei[e];
        int dst = ei[N_EDGES + e];
        float ev = ea[e];
        s += ev;
        int pos = atomicAdd(&g_cur[dst], 1);
        g_es[pos] = ((unsigned long long)__float_as_uint(ev) << 32) |
                    (unsigned long long)(unsigned)src;
    }
    #pragma unroll
    for (int o = 16; o; o >>= 1) s += __shfl_xor_sync(0xffffffffu, s, o);
    if ((threadIdx.x & 31) == 0) atomicAdd(&g_easum, s);
}

// ---------------- feature transforms ----------------
// Layer-1: x[N,2] @ Wl/Wr[2,64] (+bias). No zeroing needed anymore.
__global__ void k_transform1(const float* __restrict__ x,
                             const float* __restrict__ Wl, const float* __restrict__ bl,
                             const float* __restrict__ Wr, const float* __restrict__ br) {
    int idx = blockIdx.x * blockDim.x + threadIdx.x;
    if (idx >= N_NODES * EMB) return;
    int i = idx >> 6;
    int c = idx & 63;
    float x0 = x[2 * i + 0];
    float x1 = x[2 * i + 1];
    g_xl[idx] = fmaf(x0, Wl[c], fmaf(x1, Wl[EMB + c], bl[c]));
    g_xr[idx] = fmaf(x0, Wr[c], fmaf(x1, Wr[EMB + c], br[c]));
}

// Layer-2: h[N,64] @ Wl/Wr[64,64] (+bias). Grid-stride rows so the SMEM
// weight staging is amortized over many rows (304 blocks, not 25000).
__global__ __launch_bounds__(256) void k_transform2(
        const float* __restrict__ h,
        const float* __restrict__ Wl, const float* __restrict__ bl,
        const float* __restrict__ Wr, const float* __restrict__ br) {
    __shared__ float sWl[EMB * EMB];
    __shared__ float sWr[EMB * EMB];
    int tx = threadIdx.x & 63;
    int ty = threadIdx.x >> 6;
    for (int j = threadIdx.x; j < EMB * EMB; j += 256) {
        sWl[j] = Wl[j];
        sWr[j] = Wr[j];
    }
    __syncthreads();

    float blv = bl[tx];
    float brv = br[tx];
    for (int row = blockIdx.x * 4 + ty; row < N_NODES; row += gridDim.x * 4) {
        const float* hrow = h + row * EMB;
        float accl = blv;
        float accr = brv;
        #pragma unroll
        for (int k = 0; k < EMB; k++) {
            float hk = hrow[k];
            accl = fmaf(hk, sWl[k * EMB + tx], accl);
            accr = fmaf(hk, sWr[k * EMB + tx], accr);
        }
        int idx = row * EMB + tx;
        g_xl[idx] = accl;
        g_xr[idx] = accr;
    }
}

// ---------------- fused per-node GATv2 aggregation ----------------
// One warp per node. Halves process alternating edges; each 16-lane group
// owns all 64 channels as float4. Self-loop + softmax + bias + relu fused.
// No atomics: accumulation in registers, one coalesced write per node.
__global__ __launch_bounds__(256) void k_agg(
        const float* __restrict__ We,
        const float* __restrict__ att,
        const float* __restrict__ b,
        float* __restrict__ hout) {
    int warp = (blockIdx.x * blockDim.x + threadIdx.x) >> 5;
    if (warp >= N_NODES) return;
    int lane = threadIdx.x & 31;
    int half = lane >> 4;
    int l16  = lane & 15;

    float4 we = reinterpret_cast<const float4*>(We)[l16];
    float4 at = reinterpret_cast<const float4*>(att)[l16];

    int i    = warp;
    int off0 = g_off[i];
    int deg  = g_deg[i];

    float4 xr     = reinterpret_cast<const float4*>(g_xr)[i * 16 + l16];
    float4 xlself = reinterpret_cast<const float4*>(g_xl)[i * 16 + l16];

    // self-loop edge (attr = mean of edge_attr)
    float evm = g_easum * (1.0f / (float)N_EDGES);
    float a0 = leaky(fmaf(evm, we.x, xlself.x + xr.x));
    float a1 = leaky(fmaf(evm, we.y, xlself.y + xr.y));
    float a2 = leaky(fmaf(evm, we.z, xlself.z + xr.z));
    float a3 = leaky(fmaf(evm, we.w, xlself.w + xr.w));
    float p = fmaf(at.x, a0, fmaf(at.y, a1, fmaf(at.z, a2, at.w * a3)));
    #pragma unroll
    for (int o = 8; o; o >>= 1) p += __shfl_xor_sync(0xffffffffu, p, o);
    float exs = __expf(p);

    float denom = (half == 0) ? exs : 0.0f;
    float4 acc;
    acc.x = (half == 0) ? exs * xlself.x : 0.0f;
    acc.y = (half == 0) ? exs * xlself.y : 0.0f;
    acc.z = (half == 0) ? exs * xlself.z : 0.0f;
    acc.w = (half == 0) ? exs * xlself.w : 0.0f;

    int nit = (deg + 1) >> 1;             // uniform across the warp
    for (int t = 0; t < nit; t++) {
        int k = 2 * t + half;
        bool valid = k < deg;
        unsigned long long pk = valid ? g_es[off0 + k] : 0ull;
        int   s  = (int)(unsigned)(pk & 0xffffffffull);
        float ev = __uint_as_float((unsigned)(pk >> 32));

        float4 xl = make_float4(0.f, 0.f, 0.f, 0.f);
        if (valid) xl = reinterpret_cast<const float4*>(g_xl)[s * 16 + l16];

        float e0 = leaky(fmaf(ev, we.x, xl.x + xr.x));
        float e1 = leaky(fmaf(ev, we.y, xl.y + xr.y));
        float e2 = leaky(fmaf(ev, we.z, xl.z + xr.z));
        float e3 = leaky(fmaf(ev, we.w, xl.w + xr.w));
        float q = fmaf(at.x, e0, fmaf(at.y, e1, fmaf(at.z, e2, at.w * e3)));
        #pragma unroll
        for (int o = 8; o; o >>= 1) q += __shfl_xor_sync(0xffffffffu, q, o);

        float exv = valid ? __expf(q) : 0.0f;
        denom += exv;
        acc.x = fmaf(exv, xl.x, acc.x);
        acc.y = fmaf(exv, xl.y, acc.y);
        acc.z = fmaf(exv, xl.z, acc.z);
        acc.w = fmaf(exv, xl.w, acc.w);
    }

    // combine the two halves
    acc.x += __shfl_xor_sync(0xffffffffu, acc.x, 16);
    acc.y += __shfl_xor_sync(0xffffffffu, acc.y, 16);
    acc.z += __shfl_xor_sync(0xffffffffu, acc.z, 16);
    acc.w += __shfl_xor_sync(0xffffffffu, acc.w, 16);
    denom += __shfl_xor_sync(0xffffffffu, denom, 16);

    if (half == 0) {
        float4 bb = reinterpret_cast<const float4*>(b)[l16];
        float inv = 1.0f / denom;
        float4 out;
        out.x = fmaxf(fmaf(acc.x, inv, bb.x), 0.0f);
        out.y = fmaxf(fmaf(acc.y, inv, bb.y), 0.0f);
        out.z = fmaxf(fmaf(acc.z, inv, bb.z), 0.0f);
        out.w = fmaxf(fmaf(acc.w, inv, bb.w), 0.0f);
        reinterpret_cast<float4*>(hout)[i * 16 + l16] = out;
    }
}

// Final head: out[1,128] = h2[target] @ Wf[64,128] + bf
__global__ void k_head(const float* __restrict__ h2,
                       const int* __restrict__ tgt,
                       const float* __restrict__ Wf,
                       const float* __restrict__ bf,
                       float* __restrict__ out) {
    int j = threadIdx.x;
    int t = tgt[0];
    const float* hrow = h2 + t * EMB;
    float acc = bf[j];
    #pragma unroll
    for (int c = 0; c < EMB; c++)
        acc = fmaf(hrow[c], Wf[c * HID + j], acc);
    out[j] = acc;
}

// ---------------- launch ----------------
extern "C" void kernel_launch(void* const* d_in, const int* in_sizes, int n_in,
                              void* d_out, int out_size) {
    const float* x    = (const float*)d_in[0];
    const int*   ei   = (const int*)  d_in[1];
    const float* ea   = (const float*)d_in[2];
    const int*   tgt  = (const int*)  d_in[3];
    const float* Wl1  = (const float*)d_in[4];
    const float* bl1  = (const float*)d_in[5];
    const float* Wr1  = (const float*)d_in[6];
    const float* br1  = (const float*)d_in[7];
    const float* We1  = (const float*)d_in[8];
    const float* att1 = (const float*)d_in[9];
    const float* b1   = (const float*)d_in[10];
    const float* Wl2  = (const float*)d_in[11];
    const float* bl2  = (const float*)d_in[12];
    const float* Wr2  = (const float*)d_in[13];
    const float* br2  = (const float*)d_in[14];
    const float* We2  = (const float*)d_in[15];
    const float* att2 = (const float*)d_in[16];
    const float* b2   = (const float*)d_in[17];
    const float* Wf   = (const float*)d_in[18];
    const float* bf   = (const float*)d_in[19];
    float* out = (float*)d_out;

    float* d_h;   cudaGetSymbolAddress((void**)&d_h,   g_h);
    float* d_h2;  cudaGetSymbolAddress((void**)&d_h2,  g_h2);
    int*   d_deg; cudaGetSymbolAddress((void**)&d_deg, g_deg);
    float* d_eas; cudaGetSymbolAddress((void**)&d_eas, g_easum);

    const int NT = 256;
    int nodeBlocks = (N_NODES * EMB + NT - 1) / NT;
    int aggBlocks  = (N_NODES * 32 + NT - 1) / NT;
    int edgeBlocks = 152 * 8;

    // ---- CSR build (every call; deterministic work) ----
    cudaMemsetAsync(d_deg, 0, N_NODES * sizeof(int));
    cudaMemsetAsync(d_eas, 0, sizeof(float));
    k_hist<<<edgeBlocks, NT>>>(ei);
    k_scan<<<1, 1024>>>();
    k_scatter<<<edgeBlocks, NT>>>(ei, ea);

    // ---- layer 1 ----
    k_transform1<<<nodeBlocks, NT>>>(x, Wl1, bl1, Wr1, br1);
    k_agg<<<aggBlocks, NT>>>(We1, att1, b1, d_h);

    // ---- layer 2 ----
    k_transform2<<<304, NT>>>(d_h, Wl2, bl2, Wr2, br2);
    k_agg<<<aggBlocks, NT>>>(We2, att2, b2, d_h2);

    // ---- head ----
    k_head<<<1, HID>>>(d_h2, tgt, Wf, bf, out);
}

// round 13
// speedup vs baseline: 1.3304x; 1.3304x over previous
#include <cuda_runtime.h>
#include <cstdint>

// ---------------- problem constants ----------------
#define N_NODES 100000
#define N_EDGES 1600000
#define EMB     64
#define HID     128
#define NEG     0.2f

// ---------------- device scratch (no allocs allowed) ----------------
__device__ float g_xl[N_NODES * EMB];
__device__ float g_xr[N_NODES * EMB];
__device__ float g_h [N_NODES * EMB];   // layer accumulator, becomes h in-place
__device__ float g_h2[N_NODES * EMB];
__device__ float g_denom[N_NODES];      // per-node softmax denominator (unshifted)
__device__ float g_easum;               // sum of edge_attr (self-loop mean)

// ---------------- helpers ----------------
__device__ __forceinline__ float leaky(float a) {
    return fmaxf(a, NEG * a);           // valid for 0 < NEG < 1
}

__device__ __forceinline__ void red_add_v4(float* p, float a, float b, float c, float d) {
    asm volatile("red.global.add.v4.f32 [%0], {%1, %2, %3, %4};"
                 :: "l"(p), "f"(a), "f"(b), "f"(c), "f"(d) : "memory");
}

// ---------------- kernels ----------------
__global__ void k_zero_easum() { g_easum = 0.0f; }

__global__ void k_sum_ea(const float* __restrict__ ea) {
    float s = 0.0f;
    for (int i = blockIdx.x * blockDim.x + threadIdx.x; i < N_EDGES;
         i += gridDim.x * blockDim.x)
        s += ea[i];
    #pragma unroll
    for (int o = 16; o; o >>= 1) s += __shfl_xor_sync(0xffffffffu, s, o);
    if ((threadIdx.x & 31) == 0) atomicAdd(&g_easum, s);
}

// Layer-1 transform, vectorized: each thread produces 4 channels (float4).
// Also zeroes the accumulator and denom.
__global__ void k_transform1(const float* __restrict__ x,
                             const float* __restrict__ Wl, const float* __restrict__ bl,
                             const float* __restrict__ Wr, const float* __restrict__ br,
                             float* __restrict__ out_acc) {
    int gtid = blockIdx.x * blockDim.x + threadIdx.x;   // over N_NODES*16
    if (gtid >= N_NODES * 16) return;
    int i   = gtid >> 4;
    int l16 = gtid & 15;

    float2 xv = reinterpret_cast<const float2*>(x)[i];

    float4 wl0 = reinterpret_cast<const float4*>(Wl)[l16];
    float4 wl1 = reinterpret_cast<const float4*>(Wl + EMB)[l16];
    float4 blv = reinterpret_cast<const float4*>(bl)[l16];
    float4 wr0 = reinterpret_cast<const float4*>(Wr)[l16];
    float4 wr1 = reinterpret_cast<const float4*>(Wr + EMB)[l16];
    float4 brv = reinterpret_cast<const float4*>(br)[l16];

    float4 vl, vr;
    vl.x = fmaf(xv.x, wl0.x, fmaf(xv.y, wl1.x, blv.x));
    vl.y = fmaf(xv.x, wl0.y, fmaf(xv.y, wl1.y, blv.y));
    vl.z = fmaf(xv.x, wl0.z, fmaf(xv.y, wl1.z, blv.z));
    vl.w = fmaf(xv.x, wl0.w, fmaf(xv.y, wl1.w, blv.w));
    vr.x = fmaf(xv.x, wr0.x, fmaf(xv.y, wr1.x, brv.x));
    vr.y = fmaf(xv.x, wr0.y, fmaf(xv.y, wr1.y, brv.y));
    vr.z = fmaf(xv.x, wr0.z, fmaf(xv.y, wr1.z, brv.z));
    vr.w = fmaf(xv.x, wr0.w, fmaf(xv.y, wr1.w, brv.w));

    reinterpret_cast<float4*>(g_xl)[gtid] = vl;
    reinterpret_cast<float4*>(g_xr)[gtid] = vr;
    reinterpret_cast<float4*>(out_acc)[gtid] = make_float4(0.f, 0.f, 0.f, 0.f);
    if (l16 == 0) g_denom[i] = 0.0f;
}

// Layer-2 transform: grid-stride rows so the 32KB SMEM weight staging is
// amortized (304 persistent blocks instead of 25000).
__global__ __launch_bounds__(256) void k_transform2(
        const float* __restrict__ h,
        const float* __restrict__ Wl, const float* __restrict__ bl,
        const float* __restrict__ Wr, const float* __restrict__ br,
        float* __restrict__ out_acc) {
    __shared__ float sWl[EMB * EMB];
    __shared__ float sWr[EMB * EMB];
    int tx = threadIdx.x & 63;
    int ty = threadIdx.x >> 6;
    for (int j = threadIdx.x; j < EMB * EMB; j += 256) {
        sWl[j] = Wl[j];
        sWr[j] = Wr[j];
    }
    __syncthreads();

    float blv = bl[tx];
    float brv = br[tx];
    for (int row = blockIdx.x * 4 + ty; row < N_NODES; row += gridDim.x * 4) {
        const float* hrow = h + row * EMB;
        float accl = blv;
        float accr = brv;
        #pragma unroll
        for (int k = 0; k < EMB; k++) {
            float hk = hrow[k];
            accl = fmaf(hk, sWl[k * EMB + tx], accl);
            accr = fmaf(hk, sWr[k * EMB + tx], accr);
        }
        int idx = row * EMB + tx;
        g_xl[idx] = accl;
        g_xr[idx] = accr;
        out_acc[idx] = 0.0f;
        if (tx == 0) g_denom[row] = 0.0f;
    }
}

// FUSED edge pass, 4 edges per warp iteration (two independent half-warp
// pairs with all gathers issued up front for MLP).
// score -> ex; acc[dst] += ex * xl[src]; denom[dst] += ex.
__global__ __launch_bounds__(256) void k_edge_fused(
        const int*   __restrict__ ei,     // [2, E] row-major
        const float* __restrict__ ea,     // [E]
        const float* __restrict__ We,     // [64]
        const float* __restrict__ att,    // [64]
        float*       __restrict__ acc) {
    int lane = threadIdx.x & 31;
    int half = lane >> 4;                 // which edge of each pair
    int l16  = lane & 15;                 // channel group (4 channels)

    float4 we = reinterpret_cast<const float4*>(We)[l16];
    float4 at = reinterpret_cast<const float4*>(att)[l16];

    int warpId = (blockIdx.x * blockDim.x + threadIdx.x) >> 5;
    int nwarps = (gridDim.x * blockDim.x) >> 5;

    // N_EDGES % 4 == 0, so all four edges of each group are valid.
    for (int e0 = warpId * 4; e0 < N_EDGES; e0 += nwarps * 4) {
        int eA = e0 + half;
        int eB = e0 + 2 + half;

        // batch all index/attr loads
        int   sA = ei[eA];
        int   sB = ei[eB];
        int   dA = ei[N_EDGES + eA];
        int   dB = ei[N_EDGES + eB];
        float evA = ea[eA];
        float evB = ea[eB];

        // issue all four gathers before any compute
        float4 xlA = reinterpret_cast<const float4*>(g_xl)[sA * 16 + l16];
        float4 xrA = reinterpret_cast<const float4*>(g_xr)[dA * 16 + l16];
        float4 xlB = reinterpret_cast<const float4*>(g_xl)[sB * 16 + l16];
        float4 xrB = reinterpret_cast<const float4*>(g_xr)[dB * 16 + l16];

        // ---- edge A ----
        float a0 = leaky(fmaf(evA, we.x, xlA.x + xrA.x));
        float a1 = leaky(fmaf(evA, we.y, xlA.y + xrA.y));
        float a2 = leaky(fmaf(evA, we.z, xlA.z + xrA.z));
        float a3 = leaky(fmaf(evA, we.w, xlA.w + xrA.w));
        float pA = fmaf(at.x, a0, fmaf(at.y, a1, fmaf(at.z, a2, at.w * a3)));

        // ---- edge B ----
        float b0 = leaky(fmaf(evB, we.x, xlB.x + xrB.x));
        float b1 = leaky(fmaf(evB, we.y, xlB.y + xrB.y));
        float b2 = leaky(fmaf(evB, we.z, xlB.z + xrB.z));
        float b3 = leaky(fmaf(evB, we.w, xlB.w + xrB.w));
        float pB = fmaf(at.x, b0, fmaf(at.y, b1, fmaf(at.z, b2, at.w * b3)));

        // interleaved butterfly reductions (independent chains)
        #pragma unroll
        for (int o = 8; o; o >>= 1) {
            pA += __shfl_xor_sync(0xffffffffu, pA, o);
            pB += __shfl_xor_sync(0xffffffffu, pB, o);
        }

        float exA = __expf(pA);           // |score| small: no max-shift needed
        float exB = __expf(pB);
        if (l16 == 0) {
            atomicAdd(&g_denom[dA], exA);
            atomicAdd(&g_denom[dB], exB);
        }
        red_add_v4(acc + dA * EMB + l16 * 4,
                   exA * xlA.x, exA * xlA.y, exA * xlA.z, exA * xlA.w);
        red_add_v4(acc + dB * EMB + l16 * 4,
                   exB * xlB.x, exB * xlB.y, exB * xlB.z, exB * xlB.w);
    }
}

// Node finish: self-loop locally (no gather, no atomics), normalize, bias, relu.
__global__ __launch_bounds__(256) void k_finish(
        float* __restrict__ hbuf,
        const float* __restrict__ We,
        const float* __restrict__ att,
        const float* __restrict__ b) {
    int gtid = blockIdx.x * blockDim.x + threadIdx.x;
    int i   = gtid >> 4;
    int l16 = gtid & 15;
    if (i >= N_NODES) return;

    float evm = g_easum * (1.0f / (float)N_EDGES);
    float4 we = reinterpret_cast<const float4*>(We)[l16];
    float4 at = reinterpret_cast<const float4*>(att)[l16];
    float4 bb = reinterpret_cast<const float4*>(b)[l16];

    float4 xl = reinterpret_cast<const float4*>(g_xl)[i * 16 + l16];
    float4 xr = reinterpret_cast<const float4*>(g_xr)[i * 16 + l16];

    float a0 = leaky(fmaf(evm, we.x, xl.x + xr.x));
    float a1 = leaky(fmaf(evm, we.y, xl.y + xr.y));
    float a2 = leaky(fmaf(evm, we.z, xl.z + xr.z));
    float a3 = leaky(fmaf(evm, we.w, xl.w + xr.w));
    float p = fmaf(at.x, a0, fmaf(at.y, a1, fmaf(at.z, a2, at.w * a3)));
    #pragma unroll
    for (int o = 8; o; o >>= 1) p += __shfl_xor_sync(0xffffffffu, p, o);

    float exv = __expf(p);
    float inv = 1.0f / (g_denom[i] + exv);

    float4 acc = reinterpret_cast<const float4*>(hbuf)[i * 16 + l16];
    float4 out;
    out.x = fmaxf(fmaf(exv, xl.x, acc.x) * inv + bb.x, 0.0f);
    out.y = fmaxf(fmaf(exv, xl.y, acc.y) * inv + bb.y, 0.0f);
    out.z = fmaxf(fmaf(exv, xl.z, acc.z) * inv + bb.z, 0.0f);
    out.w = fmaxf(fmaf(exv, xl.w, acc.w) * inv + bb.w, 0.0f);
    reinterpret_cast<float4*>(hbuf)[i * 16 + l16] = out;
}

// Final head: out[1,128] = h2[target] @ Wf[64,128] + bf
__global__ void k_head(const float* __restrict__ h2,
                       const int* __restrict__ tgt,
                       const float* __restrict__ Wf,
                       const float* __restrict__ bf,
                       float* __restrict__ out) {
    int j = threadIdx.x;
    int t = tgt[0];
    const float* hrow = h2 + t * EMB;
    float acc = bf[j];
    #pragma unroll
    for (int c = 0; c < EMB; c++)
        acc = fmaf(hrow[c], Wf[c * HID + j], acc);
    out[j] = acc;
}

// ---------------- launch ----------------
extern "C" void kernel_launch(void* const* d_in, const int* in_sizes, int n_in,
                              void* d_out, int out_size) {
    const float* x    = (const float*)d_in[0];
    const int*   ei   = (const int*)  d_in[1];
    const float* ea   = (const float*)d_in[2];
    const int*   tgt  = (const int*)  d_in[3];
    const float* Wl1  = (const float*)d_in[4];
    const float* bl1  = (const float*)d_in[5];
    const float* Wr1  = (const float*)d_in[6];
    const float* br1  = (const float*)d_in[7];
    const float* We1  = (const float*)d_in[8];
    const float* att1 = (const float*)d_in[9];
    const float* b1   = (const float*)d_in[10];
    const float* Wl2  = (const float*)d_in[11];
    const float* bl2  = (const float*)d_in[12];
    const float* Wr2  = (const float*)d_in[13];
    const float* br2  = (const float*)d_in[14];
    const float* We2  = (const float*)d_in[15];
    const float* att2 = (const float*)d_in[16];
    const float* b2   = (const float*)d_in[17];
    const float* Wf   = (const float*)d_in[18];
    const float* bf   = (const float*)d_in[19];
    float* out = (float*)d_out;

    float* d_h;  cudaGetSymbolAddress((void**)&d_h,  g_h);
    float* d_h2; cudaGetSymbolAddress((void**)&d_h2, g_h2);

    const int NT = 256;
    int t1Blocks     = (N_NODES * 16 + NT - 1) / NT;
    int finishBlocks = (N_NODES * 16 + NT - 1) / NT;
    int edgeBlocks   = 152 * 8;           // grid-stride, full occupancy

    // edge_attr mean (for self-loop fill)
    k_zero_easum<<<1, 1>>>();
    k_sum_ea<<<512, NT>>>(ea);

    // ---- layer 1 ----
    k_transform1<<<t1Blocks, NT>>>(x, Wl1, bl1, Wr1, br1, d_h);
    k_edge_fused<<<edgeBlocks, NT>>>(ei, ea, We1, att1, d_h);
    k_finish<<<finishBlocks, NT>>>(d_h, We1, att1, b1);

    // ---- layer 2 ----
    k_transform2<<<304, NT>>>(d_h, Wl2, bl2, Wr2, br2, d_h2);
    k_edge_fused<<<edgeBlocks, NT>>>(ei, ea, We2, att2, d_h2);
    k_finish<<<finishBlocks, NT>>>(d_h2, We2, att2, b2);

    // ---- head ----
    k_head<<<1, HID>>>(d_h2, tgt, Wf, bf, out);
}

// round 17
// speedup vs baseline: 1.3934x; 1.0474x over previous
#include <cuda_runtime.h>
#include <cuda_fp16.h>
#include <cstdint>

// ---------------- problem constants ----------------
#define N_NODES 100000
#define N_EDGES 1600000
#define EMB     64
#define HID     128
#define NEG     0.2f

// ---------------- device scratch (no allocs allowed) ----------------
__device__ __half g_xlh[N_NODES * EMB];   // fp16 source transform table
__device__ __half g_xrh[N_NODES * EMB];   // fp16 target transform table
__device__ float  g_h [N_NODES * EMB];    // fp32 layer accumulator / h
__device__ float  g_h2[N_NODES * EMB];
__device__ float  g_denom[N_NODES];       // fp32 softmax denominator
__device__ float  g_easum;

// ---------------- helpers ----------------
__device__ __forceinline__ float leaky(float a) {
    return fmaxf(a, NEG * a);             // valid for 0 < NEG < 1
}

__device__ __forceinline__ void red_add_v4(float* p, float a, float b, float c, float d) {
    asm volatile("red.global.add.v4.f32 [%0], {%1, %2, %3, %4};"
                 :: "l"(p), "f"(a), "f"(b), "f"(c), "f"(d) : "memory");
}

// unpack 4 halves (as uint2) -> 4 floats
__device__ __forceinline__ void h4_to_f4(uint2 u, float& a, float& b, float& c, float& d) {
    float2 lo = __half22float2(*reinterpret_cast<__half2*>(&u.x));
    float2 hi = __half22float2(*reinterpret_cast<__half2*>(&u.y));
    a = lo.x; b = lo.y; c = hi.x; d = hi.y;
}

// ---------------- kernels ----------------
__global__ void k_zero_easum() { g_easum = 0.0f; }

__global__ void k_sum_ea(const float* __restrict__ ea) {
    float s = 0.0f;
    for (int i = blockIdx.x * blockDim.x + threadIdx.x; i < N_EDGES;
         i += gridDim.x * blockDim.x)
        s += ea[i];
    #pragma unroll
    for (int o = 16; o; o >>= 1) s += __shfl_xor_sync(0xffffffffu, s, o);
    if ((threadIdx.x & 31) == 0) atomicAdd(&g_easum, s);
}

// Layer-1 transform: x[N,2] @ Wl/Wr[2,64] (+bias) -> fp16 tables.
// Each thread produces 4 channels. Also zeroes acc + denom.
__global__ void k_transform1(const float* __restrict__ x,
                             const float* __restrict__ Wl, const float* __restrict__ bl,
                             const float* __restrict__ Wr, const float* __restrict__ br,
                             float* __restrict__ out_acc) {
    int gtid = blockIdx.x * blockDim.x + threadIdx.x;   // over N_NODES*16
    if (gtid >= N_NODES * 16) return;
    int i   = gtid >> 4;
    int l16 = gtid & 15;

    float2 xv = reinterpret_cast<const float2*>(x)[i];

    float4 wl0 = reinterpret_cast<const float4*>(Wl)[l16];
    float4 wl1 = reinterpret_cast<const float4*>(Wl + EMB)[l16];
    float4 blv = reinterpret_cast<const float4*>(bl)[l16];
    float4 wr0 = reinterpret_cast<const float4*>(Wr)[l16];
    float4 wr1 = reinterpret_cast<const float4*>(Wr + EMB)[l16];
    float4 brv = reinterpret_cast<const float4*>(br)[l16];

    float4 vl, vr;
    vl.x = fmaf(xv.x, wl0.x, fmaf(xv.y, wl1.x, blv.x));
    vl.y = fmaf(xv.x, wl0.y, fmaf(xv.y, wl1.y, blv.y));
    vl.z = fmaf(xv.x, wl0.z, fmaf(xv.y, wl1.z, blv.z));
    vl.w = fmaf(xv.x, wl0.w, fmaf(xv.y, wl1.w, blv.w));
    vr.x = fmaf(xv.x, wr0.x, fmaf(xv.y, wr1.x, brv.x));
    vr.y = fmaf(xv.x, wr0.y, fmaf(xv.y, wr1.y, brv.y));
    vr.z = fmaf(xv.x, wr0.z, fmaf(xv.y, wr1.z, brv.z));
    vr.w = fmaf(xv.x, wr0.w, fmaf(xv.y, wr1.w, brv.w));

    uint2 ul, ur;
    *reinterpret_cast<__half2*>(&ul.x) = __floats2half2_rn(vl.x, vl.y);
    *reinterpret_cast<__half2*>(&ul.y) = __floats2half2_rn(vl.z, vl.w);
    *reinterpret_cast<__half2*>(&ur.x) = __floats2half2_rn(vr.x, vr.y);
    *reinterpret_cast<__half2*>(&ur.y) = __floats2half2_rn(vr.z, vr.w);
    reinterpret_cast<uint2*>(g_xlh)[gtid] = ul;
    reinterpret_cast<uint2*>(g_xrh)[gtid] = ur;

    reinterpret_cast<float4*>(out_acc)[gtid] = make_float4(0.f, 0.f, 0.f, 0.f);
    if (l16 == 0) g_denom[i] = 0.0f;
}

// Layer-2 transform: h[N,64] @ Wl/Wr[64,64] (+bias) -> fp16 tables.
// Grid-stride rows (304 persistent blocks) to amortize SMEM weight staging.
__global__ __launch_bounds__(256) void k_transform2(
        const float* __restrict__ h,
        const float* __restrict__ Wl, const float* __restrict__ bl,
        const float* __restrict__ Wr, const float* __restrict__ br,
        float* __restrict__ out_acc) {
    __shared__ float sWl[EMB * EMB];
    __shared__ float sWr[EMB * EMB];
    int tx = threadIdx.x & 63;
    int ty = threadIdx.x >> 6;
    for (int j = threadIdx.x; j < EMB * EMB; j += 256) {
        sWl[j] = Wl[j];
        sWr[j] = Wr[j];
    }
    __syncthreads();

    float blv = bl[tx];
    float brv = br[tx];
    for (int row = blockIdx.x * 4 + ty; row < N_NODES; row += gridDim.x * 4) {
        const float* hrow = h + row * EMB;
        float accl = blv;
        float accr = brv;
        #pragma unroll
        for (int k = 0; k < EMB; k++) {
            float hk = hrow[k];
            accl = fmaf(hk, sWl[k * EMB + tx], accl);
            accr = fmaf(hk, sWr[k * EMB + tx], accr);
        }
        int idx = row * EMB + tx;
        g_xlh[idx] = __float2half_rn(accl);
        g_xrh[idx] = __float2half_rn(accr);
        out_acc[idx] = 0.0f;
        if (tx == 0) g_denom[row] = 0.0f;
    }
}

// FUSED edge pass on fp16 tables: score -> ex; acc[dst] += ex*xl[src] (fp32 RED);
// denom[dst] += ex. Half-warp (16 lanes) per edge, 4 fp16 channels per lane (8B).
__global__ __launch_bounds__(256) void k_edge_fused(
        const int*   __restrict__ ei,     // [2, E] row-major
        const float* __restrict__ ea,     // [E]
        const float* __restrict__ We,     // [64]
        const float* __restrict__ att,    // [64]
        float*       __restrict__ acc) {
    int lane = threadIdx.x & 31;
    int half = lane >> 4;                 // which edge of the pair
    int l16  = lane & 15;                 // channel group (4 channels)

    float4 we = reinterpret_cast<const float4*>(We)[l16];
    float4 at = reinterpret_cast<const float4*>(att)[l16];

    int warpId = (blockIdx.x * blockDim.x + threadIdx.x) >> 5;
    int nwarps = (gridDim.x * blockDim.x) >> 5;

    // N_EDGES is even; both halves always valid.
    for (int e0 = warpId * 2; e0 < N_EDGES; e0 += nwarps * 2) {
        int e = e0 + half;
        int s = ei[e];
        int d = ei[N_EDGES + e];
        float ev = ea[e];

        uint2 xlu = reinterpret_cast<const uint2*>(g_xlh)[s * 16 + l16];
        uint2 xru = reinterpret_cast<const uint2*>(g_xrh)[d * 16 + l16];

        float xl0, xl1, xl2, xl3, xr0, xr1, xr2, xr3;
        h4_to_f4(xlu, xl0, xl1, xl2, xl3);
        h4_to_f4(xru, xr0, xr1, xr2, xr3);

        float a0 = leaky(fmaf(ev, we.x, xl0 + xr0));
        float a1 = leaky(fmaf(ev, we.y, xl1 + xr1));
        float a2 = leaky(fmaf(ev, we.z, xl2 + xr2));
        float a3 = leaky(fmaf(ev, we.w, xl3 + xr3));
        float p = fmaf(at.x, a0, fmaf(at.y, a1, fmaf(at.z, a2, at.w * a3)));

        #pragma unroll
        for (int o = 8; o; o >>= 1) p += __shfl_xor_sync(0xffffffffu, p, o);

        float exv = __expf(p);            // |score| small: no max-shift needed
        if (l16 == 0) atomicAdd(&g_denom[d], exv);
        red_add_v4(acc + d * EMB + l16 * 4,
                   exv * xl0, exv * xl1, exv * xl2, exv * xl3);
    }
}

// Node finish: self-loop locally, normalize, bias, relu (fp32 output).
__global__ __launch_bounds__(256) void k_finish(
        float* __restrict__ hbuf,
        const float* __restrict__ We,
        const float* __restrict__ att,
        const float* __restrict__ b) {
    int gtid = blockIdx.x * blockDim.x + threadIdx.x;
    int i   = gtid >> 4;
    int l16 = gtid & 15;
    if (i >= N_NODES) return;

    float evm = g_easum * (1.0f / (float)N_EDGES);
    float4 we = reinterpret_cast<const float4*>(We)[l16];
    float4 at = reinterpret_cast<const float4*>(att)[l16];
    float4 bb = reinterpret_cast<const float4*>(b)[l16];

    uint2 xlu = reinterpret_cast<const uint2*>(g_xlh)[i * 16 + l16];
    uint2 xru = reinterpret_cast<const uint2*>(g_xrh)[i * 16 + l16];
    float xl0, xl1, xl2, xl3, xr0, xr1, xr2, xr3;
    h4_to_f4(xlu, xl0, xl1, xl2, xl3);
    h4_to_f4(xru, xr0, xr1, xr2, xr3);

    float a0 = leaky(fmaf(evm, we.x, xl0 + xr0));
    float a1 = leaky(fmaf(evm, we.y, xl1 + xr1));
    float a2 = leaky(fmaf(evm, we.z, xl2 + xr2));
    float a3 = leaky(fmaf(evm, we.w, xl3 + xr3));
    float p = fmaf(at.x, a0, fmaf(at.y, a1, fmaf(at.z, a2, at.w * a3)));
    #pragma unroll
    for (int o = 8; o; o >>= 1) p += __shfl_xor_sync(0xffffffffu, p, o);

    float exv = __expf(p);
    float inv = 1.0f / (g_denom[i] + exv);

    float4 acc = reinterpret_cast<const float4*>(hbuf)[i * 16 + l16];
    float4 out;
    out.x = fmaxf(fmaf(exv, xl0, acc.x) * inv + bb.x, 0.0f);
    out.y = fmaxf(fmaf(exv, xl1, acc.y) * inv + bb.y, 0.0f);
    out.z = fmaxf(fmaf(exv, xl2, acc.z) * inv + bb.z, 0.0f);
    out.w = fmaxf(fmaf(exv, xl3, acc.w) * inv + bb.w, 0.0f);
    reinterpret_cast<float4*>(hbuf)[i * 16 + l16] = out;
}

// Final head: out[1,128] = h2[target] @ Wf[64,128] + bf
__global__ void k_head(const float* __restrict__ h2,
                       const int* __restrict__ tgt,
                       const float* __restrict__ Wf,
                       const float* __restrict__ bf,
                       float* __restrict__ out) {
    int j = threadIdx.x;
    int t = tgt[0];
    const float* hrow = h2 + t * EMB;
    float acc = bf[j];
    #pragma unroll
    for (int c = 0; c < EMB; c++)
        acc = fmaf(hrow[c], Wf[c * HID + j], acc);
    out[j] = acc;
}

// ---------------- launch ----------------
extern "C" void kernel_launch(void* const* d_in, const int* in_sizes, int n_in,
                              void* d_out, int out_size) {
    const float* x    = (const float*)d_in[0];
    const int*   ei   = (const int*)  d_in[1];
    const float* ea   = (const float*)d_in[2];
    const int*   tgt  = (const int*)  d_in[3];
    const float* Wl1  = (const float*)d_in[4];
    const float* bl1  = (const float*)d_in[5];
    const float* Wr1  = (const float*)d_in[6];
    const float* br1  = (const float*)d_in[7];
    const float* We1  = (const float*)d_in[8];
    const float* att1 = (const float*)d_in[9];
    const float* b1   = (const float*)d_in[10];
    const float* Wl2  = (const float*)d_in[11];
    const float* bl2  = (const float*)d_in[12];
    const float* Wr2  = (const float*)d_in[13];
    const float* br2  = (const float*)d_in[14];
    const float* We2  = (const float*)d_in[15];
    const float* att2 = (const float*)d_in[16];
    const float* b2   = (const float*)d_in[17];
    const float* Wf   = (const float*)d_in[18];
    const float* bf   = (const float*)d_in[19];
    float* out = (float*)d_out;

    float* d_h;  cudaGetSymbolAddress((void**)&d_h,  g_h);
    float* d_h2; cudaGetSymbolAddress((void**)&d_h2, g_h2);

    const int NT = 256;
    int t1Blocks     = (N_NODES * 16 + NT - 1) / NT;
    int finishBlocks = (N_NODES * 16 + NT - 1) / NT;
    int edgeBlocks   = 152 * 8;           // grid-stride, full occupancy

    // edge_attr mean (for self-loop fill)
    k_zero_easum<<<1, 1>>>();
    k_sum_ea<<<512, NT>>>(ea);

    // ---- layer 1 ----
    k_transform1<<<t1Blocks, NT>>>(x, Wl1, bl1, Wr1, br1, d_h);
    k_edge_fused<<<edgeBlocks, NT>>>(ei, ea, We1, att1, d_h);
    k_finish<<<finishBlocks, NT>>>(d_h, We1, att1, b1);

    // ---- layer 2 ----
    k_transform2<<<304, NT>>>(d_h, Wl2, bl2, Wr2, br2, d_h2);
    k_edge_fused<<<edgeBlocks, NT>>>(ei, ea, We2, att2, d_h2);
    k_finish<<<finishBlocks, NT>>>(d_h2, We2, att2, b2);

    // ---- head ----
    k_head<<<1, HID>>>(d_h2, tgt, Wf, bf, out);
}